// round 7
// baseline (speedup 1.0000x reference)
#include <cuda_runtime.h>
#include <cuda_fp16.h>
#include <cstdint>

#define CIN 16
#define COUT 32
#define K2 9
#define MAXN 2000000
#define BT 256          // threads per block
#define NW 8            // warps per block
#define VPW 64          // voxels per warp
#define VPB 512         // voxels per block
#define STR 66          // tile channel-row stride in floats

// h1 stored as fp16, channel-PERMUTED rows: position s holds channel
// chan(s) = 4*(s>>3) + (s&3) + 16*((s>>2)&1).  128 MB -> ~L2-resident.
__device__ __half g_h1h[(size_t)MAXN * COUT];
// fused gather index: cidx = mask ? idx : -1
__device__ int g_cidx[(size_t)K2 * MAXN];

typedef unsigned long long ull;

__device__ __forceinline__ ull pack2(float a, float b) {
    ull r; asm("mov.b64 %0, {%1, %2};" : "=l"(r) : "f"(a), "f"(b)); return r;
}
__device__ __forceinline__ float2 unpack2(ull v) {
    float2 f; asm("mov.b64 {%0, %1}, %2;" : "=f"(f.x), "=f"(f.y) : "l"(v)); return f;
}
__device__ __forceinline__ ull fma2(ull a, ull b, ull c) {
    ull d; asm("fma.rn.f32x2 %0, %1, %2, %3;" : "=l"(d) : "l"(a), "l"(b), "l"(c)); return d;
}

// =====================================================================
// prologue: g_cidx[k*n+v] = mask ? idx : -1
// =====================================================================
__global__ __launch_bounds__(256)
void fuse_kernel(const int* __restrict__ idx, const unsigned* __restrict__ mask, int total) {
    int i = blockIdx.x * blockDim.x + threadIdx.x;
    int stride = gridDim.x * blockDim.x;
    int t4 = total >> 2;
    const int4* i4 = (const int4*)idx;
    const uint4* m4 = (const uint4*)mask;
    int4* c4 = (int4*)g_cidx;
    for (int j = i; j < t4; j += stride) {
        int4 v = i4[j]; uint4 m = m4[j];
        v.x = m.x ? v.x : -1;
        v.y = m.y ? v.y : -1;
        v.z = m.z ? v.z : -1;
        v.w = m.w ? v.w : -1;
        c4[j] = v;
    }
    if (i == 0)
        for (int j = t4 * 4; j < total; j++) g_cidx[j] = mask[j] ? idx[j] : -1;
}

// Thread tile: tx = lane&3 -> couts [8tx,8tx+8); ty = lane>>2 -> voxels [8ty,8ty+8)
// acc[j][p]: f32x2 over voxel pair (8ty+2p, 8ty+2p+1), cout 8tx+j.

// =====================================================================
// conv1: h1(fp16, permuted) = relu( sum_k x[cidx] @ W1[k] + b1 )
// =====================================================================
__global__ __launch_bounds__(BT)
void conv1_kernel(const float* __restrict__ x,
                  const float* __restrict__ W1,
                  const float* __restrict__ b1,
                  int n) {
    __shared__ float tiles[NW * CIN * STR];   // 33.8 KB
    const int t = threadIdx.x, lane = t & 31, w = t >> 5;
    const int tx = lane & 3, ty = lane >> 2;
    const int q4 = lane & 3, r8 = lane >> 2;
    float* xt = tiles + w * (CIN * STR);
    const int v0w = blockIdx.x * VPB + w * VPW;

    float4 st[8];
    auto load_tap = [&](int k) {
#pragma unroll
        for (int i = 0; i < 8; i++) {
            int v = v0w + r8 + 8 * i;
            int ci = (v < n) ? __ldg(g_cidx + (size_t)k * n + v) : -1;
            float4 g = make_float4(0.f, 0.f, 0.f, 0.f);
            if (ci >= 0) g = __ldg((const float4*)(x + (size_t)ci * CIN) + q4);
            st[i] = g;
        }
    };
    auto sts_tap = [&]() {      // banks 8q4+2cc+r8 : conflict-free
#pragma unroll
        for (int i = 0; i < 8; i++) {
            int vl = r8 + 8 * i, ch = 4 * q4;
            xt[(ch + 0) * STR + vl] = st[i].x;
            xt[(ch + 1) * STR + vl] = st[i].y;
            xt[(ch + 2) * STR + vl] = st[i].z;
            xt[(ch + 3) * STR + vl] = st[i].w;
        }
    };

    load_tap(0);

    ull acc[8][4];
#pragma unroll
    for (int j = 0; j < 8; j++) {
        float bv = __ldg(b1 + 8 * tx + j);
        ull bb = pack2(bv, bv);
#pragma unroll
        for (int p = 0; p < 4; p++) acc[j][p] = bb;
    }

    sts_tap();
    __syncwarp();

    for (int k = 0; k < K2; k++) {
        if (k < K2 - 1) load_tap(k + 1);
        const float* wk = W1 + k * (CIN * COUT);
#pragma unroll
        for (int c = 0; c < CIN; c++) {
            float4 wa = __ldg((const float4*)(wk + c * COUT + 8 * tx));
            float4 wb = __ldg((const float4*)(wk + c * COUT + 8 * tx) + 1);
            ull hp[4];
#pragma unroll
            for (int p = 0; p < 4; p++)
                hp[p] = *(const ull*)(xt + c * STR + 8 * ty + 2 * p);
            float wv[8] = {wa.x, wa.y, wa.z, wa.w, wb.x, wb.y, wb.z, wb.w};
#pragma unroll
            for (int j = 0; j < 8; j++) {
                ull wd = pack2(wv[j], wv[j]);
#pragma unroll
                for (int p = 0; p < 4; p++) acc[j][p] = fma2(hp[p], wd, acc[j][p]);
            }
        }
        __syncwarp();
        if (k < K2 - 1) sts_tap();
        __syncwarp();
    }

    // epilogue: relu -> fp16 permuted h1.  thread's couts 8tx+m land at
    // positions S0+{0..3} and S0+8+{0..3}, S0 = 16*(tx&1) + 4*(tx>>1).
    const int S0b = 32 * (tx & 1) + 8 * (tx >> 1);   // byte offset
#pragma unroll
    for (int p = 0; p < 4; p++) {
#pragma unroll
        for (int d = 0; d < 2; d++) {
            int v = v0w + 8 * ty + 2 * p + d;
            if (v < n) {
                float o[8];
#pragma unroll
                for (int j = 0; j < 8; j++) {
                    float2 f = unpack2(acc[j][p]);
                    o[j] = fmaxf(d ? f.y : f.x, 0.f);
                }
                __half2 a0 = __floats2half2_rn(o[0], o[1]);
                __half2 a1 = __floats2half2_rn(o[2], o[3]);
                __half2 b0 = __floats2half2_rn(o[4], o[5]);
                __half2 b1h = __floats2half2_rn(o[6], o[7]);
                char* base = (char*)(g_h1h + (size_t)v * COUT);
                uint2 ua; ua.x = *(unsigned*)&a0; ua.y = *(unsigned*)&a1;
                uint2 ub; ub.x = *(unsigned*)&b0; ub.y = *(unsigned*)&b1h;
                *(uint2*)(base + S0b) = ua;
                *(uint2*)(base + S0b + 16) = ub;
            }
        }
    }
}

// =====================================================================
// conv2 + residual: out = relu( sum_k h1[cidx] @ W2[k] + b2 + x @ Wp + bp )
// =====================================================================
__global__ __launch_bounds__(BT)
void conv2_kernel(const float* __restrict__ x,
                  const float* __restrict__ W2,
                  const float* __restrict__ b2,
                  const float* __restrict__ Wp,
                  const float* __restrict__ bp,
                  float* __restrict__ out,
                  int n) {
    extern __shared__ float sm[];           // NW * COUT * STR = 67.6 KB
    const int t = threadIdx.x, lane = t & 31, w = t >> 5;
    const int tx = lane & 3, ty = lane >> 2;
    const int q4 = lane & 3, r8 = lane >> 2;
    float* xt = sm + w * (COUT * STR);
    const int v0w = blockIdx.x * VPB + w * VPW;

    uint4 stH[8];
    auto load_tap = [&](int k) {
#pragma unroll
        for (int i = 0; i < 8; i++) {
            int v = v0w + r8 + 8 * i;
            int ci = (v < n) ? __ldg(g_cidx + (size_t)k * n + v) : -1;
            uint4 g = make_uint4(0u, 0u, 0u, 0u);
            if (ci >= 0) g = __ldg((const uint4*)(g_h1h + (size_t)ci * COUT) + q4);
            stH[i] = g;
        }
    };
    // chunk q4 holds channels {4q4+0..3, 16+4q4+0..3} (permuted h1 layout)
    // -> STS banks 8q4 + r8 + const : conflict-free
    auto sts_tap = [&]() {
#pragma unroll
        for (int i = 0; i < 8; i++) {
            int vl = r8 + 8 * i, cb = 4 * q4;
            __half2 h0 = *(__half2*)&stH[i].x;
            __half2 h1v = *(__half2*)&stH[i].y;
            __half2 h2 = *(__half2*)&stH[i].z;
            __half2 h3 = *(__half2*)&stH[i].w;
            float2 f0 = __half22float2(h0);
            float2 f1 = __half22float2(h1v);
            float2 f2 = __half22float2(h2);
            float2 f3 = __half22float2(h3);
            xt[(cb + 0) * STR + vl] = f0.x;
            xt[(cb + 1) * STR + vl] = f0.y;
            xt[(cb + 2) * STR + vl] = f1.x;
            xt[(cb + 3) * STR + vl] = f1.y;
            xt[(16 + cb + 0) * STR + vl] = f2.x;
            xt[(16 + cb + 1) * STR + vl] = f2.y;
            xt[(16 + cb + 2) * STR + vl] = f3.x;
            xt[(16 + cb + 3) * STR + vl] = f3.y;
        }
    };

    float4 stP[8];
    auto load_proj = [&]() {
#pragma unroll
        for (int i = 0; i < 8; i++) {
            int v = v0w + r8 + 8 * i;
            float4 g = make_float4(0.f, 0.f, 0.f, 0.f);
            if (v < n) g = __ldg((const float4*)(x + (size_t)v * CIN) + q4);
            stP[i] = g;
        }
    };
    auto sts_proj = [&]() {
#pragma unroll
        for (int i = 0; i < 8; i++) {
            int vl = r8 + 8 * i, ch = 4 * q4;
            xt[(ch + 0) * STR + vl] = stP[i].x;
            xt[(ch + 1) * STR + vl] = stP[i].y;
            xt[(ch + 2) * STR + vl] = stP[i].z;
            xt[(ch + 3) * STR + vl] = stP[i].w;
        }
    };

    load_proj();

    ull acc[8][4];
#pragma unroll
    for (int j = 0; j < 8; j++) {
        float bv = __ldg(b2 + 8 * tx + j) + __ldg(bp + 8 * tx + j);
        ull bb = pack2(bv, bv);
#pragma unroll
        for (int p = 0; p < 4; p++) acc[j][p] = bb;
    }

    sts_proj();
    __syncwarp();
    load_tap(0);            // tap-0 gathers overlap projection compute

    // residual projection from tile channels 0..15
#pragma unroll
    for (int c = 0; c < CIN; c++) {
        float4 wa = __ldg((const float4*)(Wp + c * COUT + 8 * tx));
        float4 wb = __ldg((const float4*)(Wp + c * COUT + 8 * tx) + 1);
        ull hp[4];
#pragma unroll
        for (int p = 0; p < 4; p++)
            hp[p] = *(const ull*)(xt + c * STR + 8 * ty + 2 * p);
        float wv[8] = {wa.x, wa.y, wa.z, wa.w, wb.x, wb.y, wb.z, wb.w};
#pragma unroll
        for (int j = 0; j < 8; j++) {
            ull wd = pack2(wv[j], wv[j]);
#pragma unroll
            for (int p = 0; p < 4; p++) acc[j][p] = fma2(hp[p], wd, acc[j][p]);
        }
    }
    __syncwarp();
    sts_tap();
    __syncwarp();

    for (int k = 0; k < K2; k++) {
        if (k < K2 - 1) load_tap(k + 1);
        const float* wk = W2 + k * (COUT * COUT);
#pragma unroll
        for (int c = 0; c < COUT; c++) {
            float4 wa = __ldg((const float4*)(wk + c * COUT + 8 * tx));
            float4 wb = __ldg((const float4*)(wk + c * COUT + 8 * tx) + 1);
            ull hp[4];
#pragma unroll
            for (int p = 0; p < 4; p++)
                hp[p] = *(const ull*)(xt + c * STR + 8 * ty + 2 * p);
            float wv[8] = {wa.x, wa.y, wa.z, wa.w, wb.x, wb.y, wb.z, wb.w};
#pragma unroll
            for (int j = 0; j < 8; j++) {
                ull wd = pack2(wv[j], wv[j]);
#pragma unroll
                for (int p = 0; p < 4; p++) acc[j][p] = fma2(hp[p], wd, acc[j][p]);
            }
        }
        __syncwarp();
        if (k < K2 - 1) sts_tap();
        __syncwarp();
    }

    // epilogue: relu -> out (fp32, natural layout)
#pragma unroll
    for (int p = 0; p < 4; p++) {
#pragma unroll
        for (int d = 0; d < 2; d++) {
            int v = v0w + 8 * ty + 2 * p + d;
            if (v < n) {
                float o[8];
#pragma unroll
                for (int j = 0; j < 8; j++) {
                    float2 f = unpack2(acc[j][p]);
                    o[j] = fmaxf(d ? f.y : f.x, 0.f);
                }
                float* op = out + (size_t)v * COUT + 8 * tx;
                *(float4*)(op)     = make_float4(o[0], o[1], o[2], o[3]);
                *(float4*)(op + 4) = make_float4(o[4], o[5], o[6], o[7]);
            }
        }
    }
}

// =====================================================================
// Launch.  Input order: x, W1, b1, W2, b2, Wp, bp, nbr_idx, nbr_mask
// =====================================================================
extern "C" void kernel_launch(void* const* d_in, const int* in_sizes, int n_in,
                              void* d_out, int out_size) {
    const float* x  = (const float*)d_in[0];
    const float* W1 = (const float*)d_in[1];
    const float* b1 = (const float*)d_in[2];
    const float* W2 = (const float*)d_in[3];
    const float* b2 = (const float*)d_in[4];
    const float* Wp = (const float*)d_in[5];
    const float* bp = (const float*)d_in[6];
    const int* nbr_idx = (const int*)d_in[7];
    const unsigned* nbr_mask = (const unsigned*)d_in[8];
    float* out = (float*)d_out;

    int n = in_sizes[0] / CIN;
    if (n > MAXN) n = MAXN;

    const int smem2 = NW * COUT * STR * 4;
    cudaFuncSetAttribute(conv2_kernel, cudaFuncAttributeMaxDynamicSharedMemorySize, smem2);

    int total = K2 * n;
    fuse_kernel<<<1024, 256>>>(nbr_idx, nbr_mask, total);

    int blocks = (n + VPB - 1) / VPB;
    conv1_kernel<<<blocks, BT>>>(x, W1, b1, n);
    conv2_kernel<<<blocks, BT, smem2>>>(x, W2, b2, Wp, bp, out, n);
}

// round 8
// speedup vs baseline: 2.5844x; 2.5844x over previous
#include <cuda_runtime.h>
#include <cuda_fp16.h>
#include <cstdint>

#define CIN 16
#define COUT 32
#define K2 9
#define MAXN 2000000

// fp16 intermediate h1 (128 MB ~ L2-resident) and fp16 copy of x (64 MB).
__device__ __half g_h1h[(size_t)MAXN * COUT];
__device__ __half g_xh[(size_t)MAXN * CIN];
// fused gather index: cidx = mask ? idx : -1
__device__ int g_cidx[(size_t)K2 * MAXN];
// L1-hot zero row (64 B) for masked / out-of-range gathers
__device__ __align__(16) unsigned g_zrow[16] = {};

typedef unsigned long long ull;

__device__ __forceinline__ ull pack2(float a, float b) {
    ull r; asm("mov.b64 %0, {%1, %2};" : "=l"(r) : "f"(a), "f"(b)); return r;
}
__device__ __forceinline__ float2 unpack2(ull v) {
    float2 f; asm("mov.b64 {%0, %1}, %2;" : "=f"(f.x), "=f"(f.y) : "l"(v)); return f;
}
__device__ __forceinline__ ull fma2(ull a, ull b, ull c) {
    ull d; asm("fma.rn.f32x2 %0, %1, %2, %3;" : "=l"(d) : "l"(a), "l"(b), "l"(c)); return d;
}

// =====================================================================
// prologue 1: cidx = mask ? idx : -1
// =====================================================================
__global__ __launch_bounds__(256)
void fuse_kernel(const int* __restrict__ idx, const unsigned* __restrict__ mask, int total) {
    int i = blockIdx.x * blockDim.x + threadIdx.x;
    int stride = gridDim.x * blockDim.x;
    int t4 = total >> 2;
    const int4* i4 = (const int4*)idx;
    const uint4* m4 = (const uint4*)mask;
    int4* c4 = (int4*)g_cidx;
    for (int j = i; j < t4; j += stride) {
        int4 v = i4[j]; uint4 m = m4[j];
        v.x = m.x ? v.x : -1;
        v.y = m.y ? v.y : -1;
        v.z = m.z ? v.z : -1;
        v.w = m.w ? v.w : -1;
        c4[j] = v;
    }
    if (i == 0)
        for (int j = t4 * 4; j < total; j++) g_cidx[j] = mask[j] ? idx[j] : -1;
}

// =====================================================================
// prologue 2: x -> fp16 copy (n*CIN is a multiple of 8)
// =====================================================================
__global__ __launch_bounds__(256)
void xh_kernel(const float* __restrict__ x, int n) {
    int total8 = n * CIN / 8;
    int stride = gridDim.x * blockDim.x;
    const float4* x4 = (const float4*)x;
    uint4* o4 = (uint4*)g_xh;
    for (int j = blockIdx.x * blockDim.x + threadIdx.x; j < total8; j += stride) {
        float4 a = __ldg(x4 + 2 * j), b = __ldg(x4 + 2 * j + 1);
        uint4 o;
        __half2 h;
        h = __floats2half2_rn(a.x, a.y); o.x = *(unsigned*)&h;
        h = __floats2half2_rn(a.z, a.w); o.y = *(unsigned*)&h;
        h = __floats2half2_rn(b.x, b.y); o.z = *(unsigned*)&h;
        h = __floats2half2_rn(b.z, b.w); o.w = *(unsigned*)&h;
        o4[j] = o;
    }
}

// =====================================================================
// conv1: h1(fp16) = relu( sum_k x_h[cidx] @ W1[k] + b1 )
// 2 voxels/thread (vA = b*512+t, vB = vA+256), cout-paired f32x2 acc.
// =====================================================================
__global__ __launch_bounds__(256, 2)
void conv1_kernel(const float* __restrict__ W1, const float* __restrict__ b1, int n) {
    __shared__ __align__(16) float ws[K2 * CIN * COUT];   // 18 KB
    __shared__ __align__(16) float bs[COUT];
    const int t = threadIdx.x;
    for (int i = t; i < K2 * CIN * COUT; i += 256) ws[i] = __ldg(W1 + i);
    if (t < COUT) bs[t] = __ldg(b1 + t);
    __syncthreads();

    const int vA = blockIdx.x * 512 + t, vB = vA + 256;
    ull acc[2][16];
#pragma unroll
    for (int o = 0; o < 16; o++) {
        ull b = *(const ull*)(bs + 2 * o);
        acc[0][o] = b; acc[1][o] = b;
    }

    for (int k = 0; k < K2; k++) {
        int ciA = (vA < n) ? __ldg(g_cidx + (size_t)k * n + vA) : -1;
        int ciB = (vB < n) ? __ldg(g_cidx + (size_t)k * n + vB) : -1;
        const uint4* pA = (ciA >= 0) ? (const uint4*)(g_xh + (size_t)ciA * CIN)
                                     : (const uint4*)g_zrow;
        const uint4* pB = (ciB >= 0) ? (const uint4*)(g_xh + (size_t)ciB * CIN)
                                     : (const uint4*)g_zrow;
        uint4 a0 = __ldg(pA), a1 = __ldg(pA + 1);
        uint4 b0 = __ldg(pB), b1v = __ldg(pB + 1);
        unsigned hA[8] = {a0.x, a0.y, a0.z, a0.w, a1.x, a1.y, a1.z, a1.w};
        unsigned hB[8] = {b0.x, b0.y, b0.z, b0.w, b1v.x, b1v.y, b1v.z, b1v.w};
        const float* wk = ws + k * (CIN * COUT);
#pragma unroll
        for (int c = 0; c < CIN; c++) {
            __half2 ha = *(__half2*)&hA[c >> 1];
            __half2 hb = *(__half2*)&hB[c >> 1];
            float fA = (c & 1) ? __high2float(ha) : __low2float(ha);
            float fB = (c & 1) ? __high2float(hb) : __low2float(hb);
            ull hhA = pack2(fA, fA), hhB = pack2(fB, fB);
            const ulonglong2* wp = (const ulonglong2*)(wk + c * COUT);
#pragma unroll
            for (int o4 = 0; o4 < 8; o4++) {
                ulonglong2 w = wp[o4];   // two f32x2 weight pairs (natural layout)
                acc[0][2 * o4]     = fma2(hhA, w.x, acc[0][2 * o4]);
                acc[0][2 * o4 + 1] = fma2(hhA, w.y, acc[0][2 * o4 + 1]);
                acc[1][2 * o4]     = fma2(hhB, w.x, acc[1][2 * o4]);
                acc[1][2 * o4 + 1] = fma2(hhB, w.y, acc[1][2 * o4 + 1]);
            }
        }
    }

    // epilogue: relu -> fp16 row (64 B, 4 STG.128)
#pragma unroll
    for (int s = 0; s < 2; s++) {
        int v = s ? vB : vA;
        if (v < n) {
            uint4 o[4];
            unsigned* ou = (unsigned*)o;
#pragma unroll
            for (int oo = 0; oo < 16; oo++) {
                float2 f = unpack2(acc[s][oo]);
                __half2 h = __floats2half2_rn(fmaxf(f.x, 0.f), fmaxf(f.y, 0.f));
                ou[oo] = *(unsigned*)&h;
            }
            uint4* dst = (uint4*)(g_h1h + (size_t)v * COUT);
            dst[0] = o[0]; dst[1] = o[1]; dst[2] = o[2]; dst[3] = o[3];
        }
    }
}

// =====================================================================
// conv2 + residual: out = relu( sum_k h1[cidx] @ W2[k] + b2 + x @ Wp + bp )
// =====================================================================
__global__ __launch_bounds__(256, 2)
void conv2_kernel(const float* __restrict__ x,
                  const float* __restrict__ W2,
                  const float* __restrict__ b2,
                  const float* __restrict__ Wp,
                  const float* __restrict__ bp,
                  float* __restrict__ out,
                  int n) {
    __shared__ __align__(16) float ws[K2 * COUT * COUT];  // 36 KB
    __shared__ __align__(16) float wp_s[CIN * COUT];      // 2 KB
    __shared__ __align__(16) float bs[COUT];
    const int t = threadIdx.x;
    for (int i = t; i < K2 * COUT * COUT; i += 256) ws[i] = __ldg(W2 + i);
    for (int i = t; i < CIN * COUT; i += 256) wp_s[i] = __ldg(Wp + i);
    if (t < COUT) bs[t] = __ldg(b2 + t) + __ldg(bp + t);
    __syncthreads();

    const int vA = blockIdx.x * 512 + t, vB = vA + 256;
    ull acc[2][16];
#pragma unroll
    for (int o = 0; o < 16; o++) {
        ull b = *(const ull*)(bs + 2 * o);
        acc[0][o] = b; acc[1][o] = b;
    }

    // ---- residual projection from own fp32 x rows (accuracy-critical path) ----
    {
        float4 xA[4], xB[4];
#pragma unroll
        for (int q = 0; q < 4; q++) {
            xA[q] = (vA < n) ? __ldg((const float4*)(x + (size_t)vA * CIN) + q)
                             : make_float4(0.f, 0.f, 0.f, 0.f);
            xB[q] = (vB < n) ? __ldg((const float4*)(x + (size_t)vB * CIN) + q)
                             : make_float4(0.f, 0.f, 0.f, 0.f);
        }
        const float* fA = (const float*)xA;
        const float* fB = (const float*)xB;
#pragma unroll
        for (int c = 0; c < CIN; c++) {
            ull hhA = pack2(fA[c], fA[c]);
            ull hhB = pack2(fB[c], fB[c]);
            const ulonglong2* wpp = (const ulonglong2*)(wp_s + c * COUT);
#pragma unroll
            for (int o4 = 0; o4 < 8; o4++) {
                ulonglong2 w = wpp[o4];
                acc[0][2 * o4]     = fma2(hhA, w.x, acc[0][2 * o4]);
                acc[0][2 * o4 + 1] = fma2(hhA, w.y, acc[0][2 * o4 + 1]);
                acc[1][2 * o4]     = fma2(hhB, w.x, acc[1][2 * o4]);
                acc[1][2 * o4 + 1] = fma2(hhB, w.y, acc[1][2 * o4 + 1]);
            }
        }
    }

    // ---- 9 taps over fp16 h1 gathers ----
    for (int k = 0; k < K2; k++) {
        int ciA = (vA < n) ? __ldg(g_cidx + (size_t)k * n + vA) : -1;
        int ciB = (vB < n) ? __ldg(g_cidx + (size_t)k * n + vB) : -1;
        const uint4* pA = (ciA >= 0) ? (const uint4*)(g_h1h + (size_t)ciA * COUT)
                                     : (const uint4*)g_zrow;
        const uint4* pB = (ciB >= 0) ? (const uint4*)(g_h1h + (size_t)ciB * COUT)
                                     : (const uint4*)g_zrow;
        // NOTE: g_zrow is 64 B, exactly one fp16 row — safe for all 4 chunks.
        uint4 ra[4], rb[4];
#pragma unroll
        for (int q = 0; q < 4; q++) { ra[q] = __ldg(pA + q); rb[q] = __ldg(pB + q); }
        const unsigned* hA = (const unsigned*)ra;
        const unsigned* hB = (const unsigned*)rb;
        const float* wk = ws + k * (COUT * COUT);
#pragma unroll
        for (int c = 0; c < COUT; c++) {
            __half2 ha = *(__half2*)&hA[c >> 1];
            __half2 hb = *(__half2*)&hB[c >> 1];
            float fA = (c & 1) ? __high2float(ha) : __low2float(ha);
            float fB = (c & 1) ? __high2float(hb) : __low2float(hb);
            ull hhA = pack2(fA, fA), hhB = pack2(fB, fB);
            const ulonglong2* wpt = (const ulonglong2*)(wk + c * COUT);
#pragma unroll
            for (int o4 = 0; o4 < 8; o4++) {
                ulonglong2 w = wpt[o4];
                acc[0][2 * o4]     = fma2(hhA, w.x, acc[0][2 * o4]);
                acc[0][2 * o4 + 1] = fma2(hhA, w.y, acc[0][2 * o4 + 1]);
                acc[1][2 * o4]     = fma2(hhB, w.x, acc[1][2 * o4]);
                acc[1][2 * o4 + 1] = fma2(hhB, w.y, acc[1][2 * o4 + 1]);
            }
        }
    }

    // epilogue: relu -> fp32 out rows (128 B, 8 STG.128)
#pragma unroll
    for (int s = 0; s < 2; s++) {
        int v = s ? vB : vA;
        if (v < n) {
            float* op = out + (size_t)v * COUT;
#pragma unroll
            for (int o4 = 0; o4 < 8; o4++) {
                float2 f0 = unpack2(acc[s][2 * o4]);
                float2 f1 = unpack2(acc[s][2 * o4 + 1]);
                *(float4*)(op + 4 * o4) =
                    make_float4(fmaxf(f0.x, 0.f), fmaxf(f0.y, 0.f),
                                fmaxf(f1.x, 0.f), fmaxf(f1.y, 0.f));
            }
        }
    }
}

// =====================================================================
// Launch.  Input order: x, W1, b1, W2, b2, Wp, bp, nbr_idx, nbr_mask
// =====================================================================
extern "C" void kernel_launch(void* const* d_in, const int* in_sizes, int n_in,
                              void* d_out, int out_size) {
    const float* x  = (const float*)d_in[0];
    const float* W1 = (const float*)d_in[1];
    const float* b1 = (const float*)d_in[2];
    const float* W2 = (const float*)d_in[3];
    const float* b2 = (const float*)d_in[4];
    const float* Wp = (const float*)d_in[5];
    const float* bp = (const float*)d_in[6];
    const int* nbr_idx = (const int*)d_in[7];
    const unsigned* nbr_mask = (const unsigned*)d_in[8];
    float* out = (float*)d_out;

    int n = in_sizes[0] / CIN;
    if (n > MAXN) n = MAXN;

    fuse_kernel<<<1024, 256>>>(nbr_idx, nbr_mask, K2 * n);
    xh_kernel<<<512, 256>>>(x, n);

    int blocks = (n + 511) / 512;
    conv1_kernel<<<blocks, 256>>>(W1, b1, n);
    conv2_kernel<<<blocks, 256>>>(x, W2, b2, Wp, bp, out, n);
}

// round 9
// speedup vs baseline: 2.6345x; 1.0194x over previous
#include <cuda_runtime.h>
#include <cuda_fp16.h>
#include <cstdint>

#define CIN 16
#define COUT 32
#define K2 9
#define MAXN 2000000

// fp16 intermediate h1 (128 MB ~ L2-resident) and fp16 copy of x (64 MB).
__device__ __half g_h1h[(size_t)MAXN * COUT];
__device__ __half g_xh[(size_t)MAXN * CIN];
// fused gather index: cidx = mask ? idx : -1
__device__ int g_cidx[(size_t)K2 * MAXN];
// L1-hot zero row (64 B) for masked / out-of-range gathers
__device__ __align__(64) unsigned g_zrow[16] = {};

typedef unsigned long long ull;

__device__ __forceinline__ ull pack2(float a, float b) {
    ull r; asm("mov.b64 %0, {%1, %2};" : "=l"(r) : "f"(a), "f"(b)); return r;
}
__device__ __forceinline__ float2 unpack2(ull v) {
    float2 f; asm("mov.b64 {%0, %1}, %2;" : "=f"(f.x), "=f"(f.y) : "l"(v)); return f;
}
__device__ __forceinline__ ull fma2(ull a, ull b, ull c) {
    ull d; asm("fma.rn.f32x2 %0, %1, %2, %3;" : "=l"(d) : "l"(a), "l"(b), "l"(c)); return d;
}
// 256-bit non-coherent global load (sm_100+): one instruction = 32 B/lane.
__device__ __forceinline__ void ldg256(const void* p, uint4& a, uint4& b) {
    asm("ld.global.nc.v8.b32 {%0,%1,%2,%3,%4,%5,%6,%7}, [%8];"
        : "=r"(a.x), "=r"(a.y), "=r"(a.z), "=r"(a.w),
          "=r"(b.x), "=r"(b.y), "=r"(b.z), "=r"(b.w)
        : "l"(p));
}

// =====================================================================
// prologue 1: cidx = mask ? idx : -1
// =====================================================================
__global__ __launch_bounds__(256)
void fuse_kernel(const int* __restrict__ idx, const unsigned* __restrict__ mask, int total) {
    int i = blockIdx.x * blockDim.x + threadIdx.x;
    int stride = gridDim.x * blockDim.x;
    int t4 = total >> 2;
    const int4* i4 = (const int4*)idx;
    const uint4* m4 = (const uint4*)mask;
    int4* c4 = (int4*)g_cidx;
    for (int j = i; j < t4; j += stride) {
        int4 v = i4[j]; uint4 m = m4[j];
        v.x = m.x ? v.x : -1;
        v.y = m.y ? v.y : -1;
        v.z = m.z ? v.z : -1;
        v.w = m.w ? v.w : -1;
        c4[j] = v;
    }
    if (i == 0)
        for (int j = t4 * 4; j < total; j++) g_cidx[j] = mask[j] ? idx[j] : -1;
}

// =====================================================================
// prologue 2: x -> fp16 copy
// =====================================================================
__global__ __launch_bounds__(256)
void xh_kernel(const float* __restrict__ x, int n) {
    int total8 = n * CIN / 8;
    int stride = gridDim.x * blockDim.x;
    const float4* x4 = (const float4*)x;
    uint4* o4 = (uint4*)g_xh;
    for (int j = blockIdx.x * blockDim.x + threadIdx.x; j < total8; j += stride) {
        float4 a = __ldg(x4 + 2 * j), b = __ldg(x4 + 2 * j + 1);
        uint4 o;
        __half2 h;
        h = __floats2half2_rn(a.x, a.y); o.x = *(unsigned*)&h;
        h = __floats2half2_rn(a.z, a.w); o.y = *(unsigned*)&h;
        h = __floats2half2_rn(b.x, b.y); o.z = *(unsigned*)&h;
        h = __floats2half2_rn(b.z, b.w); o.w = *(unsigned*)&h;
        o4[j] = o;
    }
}

// =====================================================================
// conv1: h1(fp16) = relu( sum_k x_h[cidx] @ W1[k] + b1 )
// 2 voxels/thread (vA = b*512+t, vB = vA+256), cout-paired f32x2 acc.
// =====================================================================
__global__ __launch_bounds__(256, 2)
void conv1_kernel(const float* __restrict__ W1, const float* __restrict__ b1, int n) {
    __shared__ __align__(16) float ws[K2 * CIN * COUT];   // 18 KB
    __shared__ __align__(16) float bs[COUT];
    const int t = threadIdx.x;
    for (int i = t; i < K2 * CIN * COUT; i += 256) ws[i] = __ldg(W1 + i);
    if (t < COUT) bs[t] = __ldg(b1 + t);
    __syncthreads();

    const int vA = blockIdx.x * 512 + t, vB = vA + 256;
    ull acc[2][16];
#pragma unroll
    for (int o = 0; o < 16; o++) {
        ull b = *(const ull*)(bs + 2 * o);
        acc[0][o] = b; acc[1][o] = b;
    }

    for (int k = 0; k < K2; k++) {
        int ciA = (vA < n) ? __ldg(g_cidx + (size_t)k * n + vA) : -1;
        int ciB = (vB < n) ? __ldg(g_cidx + (size_t)k * n + vB) : -1;
        const void* pA = (ciA >= 0) ? (const void*)(g_xh + (size_t)ciA * CIN)
                                    : (const void*)g_zrow;
        const void* pB = (ciB >= 0) ? (const void*)(g_xh + (size_t)ciB * CIN)
                                    : (const void*)g_zrow;
        uint4 a0, a1, b0, b1v;
        ldg256(pA, a0, a1);           // full 32 B fp16 row in ONE instruction
        ldg256(pB, b0, b1v);
        unsigned hA[8] = {a0.x, a0.y, a0.z, a0.w, a1.x, a1.y, a1.z, a1.w};
        unsigned hB[8] = {b0.x, b0.y, b0.z, b0.w, b1v.x, b1v.y, b1v.z, b1v.w};
        const float* wk = ws + k * (CIN * COUT);
#pragma unroll
        for (int c = 0; c < CIN; c++) {
            __half2 ha = *(__half2*)&hA[c >> 1];
            __half2 hb = *(__half2*)&hB[c >> 1];
            float fA = (c & 1) ? __high2float(ha) : __low2float(ha);
            float fB = (c & 1) ? __high2float(hb) : __low2float(hb);
            ull hhA = pack2(fA, fA), hhB = pack2(fB, fB);
            const ulonglong2* wp = (const ulonglong2*)(wk + c * COUT);
#pragma unroll
            for (int o4 = 0; o4 < 8; o4++) {
                ulonglong2 w = wp[o4];
                acc[0][2 * o4]     = fma2(hhA, w.x, acc[0][2 * o4]);
                acc[0][2 * o4 + 1] = fma2(hhA, w.y, acc[0][2 * o4 + 1]);
                acc[1][2 * o4]     = fma2(hhB, w.x, acc[1][2 * o4]);
                acc[1][2 * o4 + 1] = fma2(hhB, w.y, acc[1][2 * o4 + 1]);
            }
        }
    }

    // epilogue: relu -> fp16 row (64 B)
#pragma unroll
    for (int s = 0; s < 2; s++) {
        int v = s ? vB : vA;
        if (v < n) {
            uint4 o[4];
            unsigned* ou = (unsigned*)o;
#pragma unroll
            for (int oo = 0; oo < 16; oo++) {
                float2 f = unpack2(acc[s][oo]);
                __half2 h = __floats2half2_rn(fmaxf(f.x, 0.f), fmaxf(f.y, 0.f));
                ou[oo] = *(unsigned*)&h;
            }
            uint4* dst = (uint4*)(g_h1h + (size_t)v * COUT);
            dst[0] = o[0]; dst[1] = o[1]; dst[2] = o[2]; dst[3] = o[3];
        }
    }
}

// =====================================================================
// conv2 + residual: out = relu( sum_k h1[cidx] @ W2[k] + b2 + x @ Wp + bp )
// =====================================================================
__global__ __launch_bounds__(256, 2)
void conv2_kernel(const float* __restrict__ x,
                  const float* __restrict__ W2,
                  const float* __restrict__ b2,
                  const float* __restrict__ Wp,
                  const float* __restrict__ bp,
                  float* __restrict__ out,
                  int n) {
    __shared__ __align__(16) float ws[K2 * COUT * COUT];  // 36 KB
    __shared__ __align__(16) float wp_s[CIN * COUT];      // 2 KB
    __shared__ __align__(16) float bs[COUT];
    const int t = threadIdx.x;
    for (int i = t; i < K2 * COUT * COUT; i += 256) ws[i] = __ldg(W2 + i);
    for (int i = t; i < CIN * COUT; i += 256) wp_s[i] = __ldg(Wp + i);
    if (t < COUT) bs[t] = __ldg(b2 + t) + __ldg(bp + t);
    __syncthreads();

    const int vA = blockIdx.x * 512 + t, vB = vA + 256;
    ull acc[2][16];
#pragma unroll
    for (int o = 0; o < 16; o++) {
        ull b = *(const ull*)(bs + 2 * o);
        acc[0][o] = b; acc[1][o] = b;
    }

    // ---- residual projection from own fp32 x rows (accuracy-critical path) ----
    {
        float4 xA[4], xB[4];
#pragma unroll
        for (int q = 0; q < 4; q++) {
            xA[q] = (vA < n) ? __ldg((const float4*)(x + (size_t)vA * CIN) + q)
                             : make_float4(0.f, 0.f, 0.f, 0.f);
            xB[q] = (vB < n) ? __ldg((const float4*)(x + (size_t)vB * CIN) + q)
                             : make_float4(0.f, 0.f, 0.f, 0.f);
        }
        const float* fA = (const float*)xA;
        const float* fB = (const float*)xB;
#pragma unroll
        for (int c = 0; c < CIN; c++) {
            ull hhA = pack2(fA[c], fA[c]);
            ull hhB = pack2(fB[c], fB[c]);
            const ulonglong2* wpp = (const ulonglong2*)(wp_s + c * COUT);
#pragma unroll
            for (int o4 = 0; o4 < 8; o4++) {
                ulonglong2 w = wpp[o4];
                acc[0][2 * o4]     = fma2(hhA, w.x, acc[0][2 * o4]);
                acc[0][2 * o4 + 1] = fma2(hhA, w.y, acc[0][2 * o4 + 1]);
                acc[1][2 * o4]     = fma2(hhB, w.x, acc[1][2 * o4]);
                acc[1][2 * o4 + 1] = fma2(hhB, w.y, acc[1][2 * o4 + 1]);
            }
        }
    }

    // ---- 9 taps over fp16 h1 gathers (64 B row = 2x LDG.256) ----
    for (int k = 0; k < K2; k++) {
        int ciA = (vA < n) ? __ldg(g_cidx + (size_t)k * n + vA) : -1;
        int ciB = (vB < n) ? __ldg(g_cidx + (size_t)k * n + vB) : -1;
        const char* pA = (ciA >= 0) ? (const char*)(g_h1h + (size_t)ciA * COUT)
                                    : (const char*)g_zrow;
        const char* pB = (ciB >= 0) ? (const char*)(g_h1h + (size_t)ciB * COUT)
                                    : (const char*)g_zrow;
        uint4 ra[4], rb[4];
        ldg256(pA,      ra[0], ra[1]);
        ldg256(pA + 32, ra[2], ra[3]);
        ldg256(pB,      rb[0], rb[1]);
        ldg256(pB + 32, rb[2], rb[3]);
        const unsigned* hA = (const unsigned*)ra;
        const unsigned* hB = (const unsigned*)rb;
        const float* wk = ws + k * (COUT * COUT);
#pragma unroll
        for (int c = 0; c < COUT; c++) {
            __half2 ha = *(__half2*)&hA[c >> 1];
            __half2 hb = *(__half2*)&hB[c >> 1];
            float fA = (c & 1) ? __high2float(ha) : __low2float(ha);
            float fB = (c & 1) ? __high2float(hb) : __low2float(hb);
            ull hhA = pack2(fA, fA), hhB = pack2(fB, fB);
            const ulonglong2* wpt = (const ulonglong2*)(wk + c * COUT);
#pragma unroll
            for (int o4 = 0; o4 < 8; o4++) {
                ulonglong2 w = wpt[o4];
                acc[0][2 * o4]     = fma2(hhA, w.x, acc[0][2 * o4]);
                acc[0][2 * o4 + 1] = fma2(hhA, w.y, acc[0][2 * o4 + 1]);
                acc[1][2 * o4]     = fma2(hhB, w.x, acc[1][2 * o4]);
                acc[1][2 * o4 + 1] = fma2(hhB, w.y, acc[1][2 * o4 + 1]);
            }
        }
    }

    // epilogue: relu -> fp32 out rows
#pragma unroll
    for (int s = 0; s < 2; s++) {
        int v = s ? vB : vA;
        if (v < n) {
            float* op = out + (size_t)v * COUT;
#pragma unroll
            for (int o4 = 0; o4 < 8; o4++) {
                float2 f0 = unpack2(acc[s][2 * o4]);
                float2 f1 = unpack2(acc[s][2 * o4 + 1]);
                *(float4*)(op + 4 * o4) =
                    make_float4(fmaxf(f0.x, 0.f), fmaxf(f0.y, 0.f),
                                fmaxf(f1.x, 0.f), fmaxf(f1.y, 0.f));
            }
        }
    }
}

// =====================================================================
// Launch.  Input order: x, W1, b1, W2, b2, Wp, bp, nbr_idx, nbr_mask
// =====================================================================
extern "C" void kernel_launch(void* const* d_in, const int* in_sizes, int n_in,
                              void* d_out, int out_size) {
    const float* x  = (const float*)d_in[0];
    const float* W1 = (const float*)d_in[1];
    const float* b1 = (const float*)d_in[2];
    const float* W2 = (const float*)d_in[3];
    const float* b2 = (const float*)d_in[4];
    const float* Wp = (const float*)d_in[5];
    const float* bp = (const float*)d_in[6];
    const int* nbr_idx = (const int*)d_in[7];
    const unsigned* nbr_mask = (const unsigned*)d_in[8];
    float* out = (float*)d_out;

    int n = in_sizes[0] / CIN;
    if (n > MAXN) n = MAXN;

    fuse_kernel<<<1024, 256>>>(nbr_idx, nbr_mask, K2 * n);
    xh_kernel<<<512, 256>>>(x, n);

    int blocks = (n + 511) / 512;
    conv1_kernel<<<blocks, 256>>>(W1, b1, n);
    conv2_kernel<<<blocks, 256>>>(x, W2, b2, Wp, bp, out, n);
}

// round 10
// speedup vs baseline: 4.5897x; 1.7421x over previous
#include <cuda_runtime.h>
#include <cuda_fp16.h>
#include <cstdint>

#define CIN 16
#define COUT 32
#define K2 9
#define MAXN 2000000
#define WSTR 40    // weight SMEM row stride in halves (80 B)
#define A2B 80     // conv2 A-tile row stride bytes
#define A1B 48     // conv1 A-tile row stride bytes

// fp16 intermediate h1 (128 MB ~ L2-resident) and fp16 copy of x (64 MB).
__device__ __align__(256) __half g_h1h[(size_t)MAXN * COUT];
__device__ __align__(256) __half g_xh[(size_t)MAXN * CIN];
// fused gather index: cidx = mask ? idx : -1
__device__ int g_cidx[(size_t)K2 * MAXN];
// fp16 weights (compact)
__device__ __half g_w1h[K2 * CIN * COUT];
__device__ __half g_w2h[K2 * COUT * COUT];
__device__ __half g_wph[CIN * COUT];
// zero row (64 B) for masked / out-of-range gathers
__device__ __align__(64) unsigned g_zrow[16] = {};

// ---- PTX wrappers ----
__device__ __forceinline__ void ldg256(const void* p, uint4& a, uint4& b) {
    asm("ld.global.nc.v8.b32 {%0,%1,%2,%3,%4,%5,%6,%7}, [%8];"
        : "=r"(a.x), "=r"(a.y), "=r"(a.z), "=r"(a.w),
          "=r"(b.x), "=r"(b.y), "=r"(b.z), "=r"(b.w)
        : "l"(p));
}
__device__ __forceinline__ void ldsm4(unsigned r[4], unsigned addr) {
    asm volatile("ldmatrix.sync.aligned.m8n8.x4.shared.b16 {%0,%1,%2,%3}, [%4];"
                 : "=r"(r[0]), "=r"(r[1]), "=r"(r[2]), "=r"(r[3]) : "r"(addr));
}
__device__ __forceinline__ void ldsm4t(unsigned r[4], unsigned addr) {
    asm volatile("ldmatrix.sync.aligned.m8n8.x4.trans.shared.b16 {%0,%1,%2,%3}, [%4];"
                 : "=r"(r[0]), "=r"(r[1]), "=r"(r[2]), "=r"(r[3]) : "r"(addr));
}
__device__ __forceinline__ void mma16816(float c[4], const unsigned a[4],
                                         unsigned b0, unsigned b1) {
    asm("mma.sync.aligned.m16n8k16.row.col.f32.f16.f16.f32 "
        "{%0,%1,%2,%3}, {%4,%5,%6,%7}, {%8,%9}, {%0,%1,%2,%3};"
        : "+f"(c[0]), "+f"(c[1]), "+f"(c[2]), "+f"(c[3])
        : "r"(a[0]), "r"(a[1]), "r"(a[2]), "r"(a[3]), "r"(b0), "r"(b1));
}

// =====================================================================
// prologues
// =====================================================================
__global__ __launch_bounds__(256)
void fuse_kernel(const int* __restrict__ idx, const unsigned* __restrict__ mask, int total) {
    int i = blockIdx.x * blockDim.x + threadIdx.x;
    int stride = gridDim.x * blockDim.x;
    int t4 = total >> 2;
    const int4* i4 = (const int4*)idx;
    const uint4* m4 = (const uint4*)mask;
    int4* c4 = (int4*)g_cidx;
    for (int j = i; j < t4; j += stride) {
        int4 v = i4[j]; uint4 m = m4[j];
        v.x = m.x ? v.x : -1;  v.y = m.y ? v.y : -1;
        v.z = m.z ? v.z : -1;  v.w = m.w ? v.w : -1;
        c4[j] = v;
    }
    if (i == 0)
        for (int j = t4 * 4; j < total; j++) g_cidx[j] = mask[j] ? idx[j] : -1;
}

__global__ __launch_bounds__(256)
void xh_kernel(const float* __restrict__ x, int n) {
    int total8 = n * CIN / 8;
    int stride = gridDim.x * blockDim.x;
    const float4* x4 = (const float4*)x;
    uint4* o4 = (uint4*)g_xh;
    for (int j = blockIdx.x * blockDim.x + threadIdx.x; j < total8; j += stride) {
        float4 a = __ldg(x4 + 2 * j), b = __ldg(x4 + 2 * j + 1);
        uint4 o; __half2 h;
        h = __floats2half2_rn(a.x, a.y); o.x = *(unsigned*)&h;
        h = __floats2half2_rn(a.z, a.w); o.y = *(unsigned*)&h;
        h = __floats2half2_rn(b.x, b.y); o.z = *(unsigned*)&h;
        h = __floats2half2_rn(b.z, b.w); o.w = *(unsigned*)&h;
        o4[j] = o;
    }
}

__global__ __launch_bounds__(256)
void wcvt_kernel(const float* __restrict__ W1, const float* __restrict__ W2,
                 const float* __restrict__ Wp) {
    int i = blockIdx.x * 256 + threadIdx.x;
    if (i < K2 * CIN * COUT)  g_w1h[i] = __float2half(W1[i]);
    if (i < K2 * COUT * COUT) g_w2h[i] = __float2half(W2[i]);
    if (i < CIN * COUT)       g_wph[i] = __float2half(Wp[i]);
}

// =====================================================================
// conv1: h1(fp16) = relu( sum_k x_h[cidx] @ W1[k] + b1 )
// 1 voxel/thread; warp = 32 voxels x 32 couts; K=16 per tap -> 8 HMMA/tap.
// =====================================================================
__global__ __launch_bounds__(256, 3)
void conv1_kernel(const float* __restrict__ b1, int n) {
    __shared__ __half wsm[K2 * CIN * WSTR];      // 9*16*40*2 = 11.5 KB
    __shared__ float bsm[COUT];
    __shared__ __align__(16) __half atile[8 * 32 * (A1B / 2)];   // 12 KB

    const int t = threadIdx.x, lane = t & 31, w = t >> 5;
    for (int i = t; i < K2 * CIN * COUT; i += 256) {
        int row = i >> 5, cc = i & 31;
        wsm[row * WSTR + cc] = g_w1h[i];
    }
    if (t < COUT) bsm[t] = __ldg(b1 + t);
    __syncthreads();

    const int grp = lane >> 2, tig = lane & 3;
    const int sub = lane & 7, ti = lane >> 3;
    const int v0w = blockIdx.x * 256 + w * 32;
    const int v = v0w + lane;

    char* arow_c = (char*)atile + w * 32 * A1B + lane * A1B;
    const unsigned abase =
        (unsigned)__cvta_generic_to_shared((char*)atile + w * 32 * A1B);
    const unsigned wb0 = (unsigned)__cvta_generic_to_shared(wsm);
    const int lro = sub + ((ti & 1) << 3);      // ldsm row offset within tile
    const int lco = (ti >> 1) << 4;             // ldsm col byte offset

    float acc[2][4][4];
#pragma unroll
    for (int m = 0; m < 2; m++)
#pragma unroll
        for (int nt = 0; nt < 4; nt++) {
            float c0 = bsm[8 * nt + 2 * tig], c1 = bsm[8 * nt + 2 * tig + 1];
            acc[m][nt][0] = c0; acc[m][nt][1] = c1;
            acc[m][nt][2] = c0; acc[m][nt][3] = c1;
        }

    // prefetch tap 0
    uint4 g[2][2];
    {
        int ci = (v < n) ? __ldg(g_cidx + v) : -1;
        const void* p = (ci >= 0) ? (const void*)(g_xh + (size_t)ci * CIN)
                                  : (const void*)g_zrow;
        ldg256(p, g[0][0], g[0][1]);
    }

#pragma unroll
    for (int k = 0; k < K2; k++) {
        uint4* cur = g[k & 1];
        ((uint4*)arow_c)[0] = cur[0];
        ((uint4*)arow_c)[1] = cur[1];
        __syncwarp();
        if (k < K2 - 1) {
            int ci = (v < n) ? __ldg(g_cidx + (size_t)(k + 1) * n + v) : -1;
            const void* p = (ci >= 0) ? (const void*)(g_xh + (size_t)ci * CIN)
                                      : (const void*)g_zrow;
            ldg256(p, g[(k + 1) & 1][0], g[(k + 1) & 1][1]);
        }
        unsigned bw[8];
        unsigned wtap = wb0 + k * (CIN * WSTR * 2) + lro * (WSTR * 2) + lco;
        ldsm4t(bw,     wtap);        // n-tiles 0,1
        ldsm4t(bw + 4, wtap + 32);   // n-tiles 2,3
        unsigned av[4];
#pragma unroll
        for (int m = 0; m < 2; m++) {
            ldsm4(av, abase + (16 * m + lro) * A1B + lco);
            mma16816(acc[m][0], av, bw[0], bw[1]);
            mma16816(acc[m][1], av, bw[2], bw[3]);
            mma16816(acc[m][2], av, bw[4], bw[5]);
            mma16816(acc[m][3], av, bw[6], bw[7]);
        }
        __syncwarp();
    }

    // epilogue: relu -> fp16 h1 (scattered half2 stores)
#pragma unroll
    for (int m = 0; m < 2; m++) {
        int vg0 = v0w + 16 * m + grp, vg1 = vg0 + 8;
#pragma unroll
        for (int nt = 0; nt < 4; nt++) {
            const float* a = acc[m][nt];
            if (vg0 < n) {
                __half2 h = __floats2half2_rn(fmaxf(a[0], 0.f), fmaxf(a[1], 0.f));
                *(__half2*)(g_h1h + (size_t)vg0 * COUT + 8 * nt + 2 * tig) = h;
            }
            if (vg1 < n) {
                __half2 h = __floats2half2_rn(fmaxf(a[2], 0.f), fmaxf(a[3], 0.f));
                *(__half2*)(g_h1h + (size_t)vg1 * COUT + 8 * nt + 2 * tig) = h;
            }
        }
    }
}

// =====================================================================
// conv2 + residual: out = relu( sum_k h1[cidx] @ W2[k] + x_h @ Wp + b2 + bp )
// K=32 per tap -> 16 HMMA/tap; proj = extra K=16 tap.
// =====================================================================
__global__ __launch_bounds__(256, 2)
void conv2_kernel(const float* __restrict__ b2, const float* __restrict__ bp,
                  float* __restrict__ out, int n) {
    __shared__ __half wsm[K2 * COUT * WSTR];     // 23 KB
    __shared__ __half wpsm[CIN * WSTR];          // 1.3 KB
    __shared__ float bsm[COUT];
    __shared__ __align__(16) __half atile[8 * 32 * (A2B / 2)];  // 20 KB

    const int t = threadIdx.x, lane = t & 31, w = t >> 5;
    for (int i = t; i < K2 * COUT * COUT; i += 256) {
        int row = i >> 5, cc = i & 31;
        wsm[row * WSTR + cc] = g_w2h[i];
    }
    for (int i = t; i < CIN * COUT; i += 256) {
        int row = i >> 5, cc = i & 31;
        wpsm[row * WSTR + cc] = g_wph[i];
    }
    if (t < COUT) bsm[t] = __ldg(b2 + t) + __ldg(bp + t);
    __syncthreads();

    const int grp = lane >> 2, tig = lane & 3;
    const int sub = lane & 7, ti = lane >> 3;
    const int v0w = blockIdx.x * 256 + w * 32;
    const int v = v0w + lane;

    char* arow_c = (char*)atile + w * 32 * A2B + lane * A2B;
    const unsigned abase =
        (unsigned)__cvta_generic_to_shared((char*)atile + w * 32 * A2B);
    const unsigned wb0 = (unsigned)__cvta_generic_to_shared(wsm);
    const unsigned wpb = (unsigned)__cvta_generic_to_shared(wpsm);
    const int lro = sub + ((ti & 1) << 3);
    const int lco = (ti >> 1) << 4;

    float acc[2][4][4];
#pragma unroll
    for (int m = 0; m < 2; m++)
#pragma unroll
        for (int nt = 0; nt < 4; nt++) {
            float c0 = bsm[8 * nt + 2 * tig], c1 = bsm[8 * nt + 2 * tig + 1];
            acc[m][nt][0] = c0; acc[m][nt][1] = c1;
            acc[m][nt][2] = c0; acc[m][nt][3] = c1;
        }

    // ---- projection tap (K=16) from own fp16 x row ----
    {
        uint4 px0, px1;
        const void* xp = (v < n) ? (const void*)(g_xh + (size_t)v * CIN)
                                 : (const void*)g_zrow;
        ldg256(xp, px0, px1);
        ((uint4*)arow_c)[0] = px0;
        ((uint4*)arow_c)[1] = px1;
        __syncwarp();
    }

    // prefetch tap 0 gathers (overlap with proj MMA)
    uint4 g[2][4];
    {
        int ci = (v < n) ? __ldg(g_cidx + v) : -1;
        const char* p = (ci >= 0) ? (const char*)(g_h1h + (size_t)ci * COUT)
                                  : (const char*)g_zrow;
        ldg256(p,      g[0][0], g[0][1]);
        ldg256(p + 32, g[0][2], g[0][3]);
    }

    // proj MMA
    {
        unsigned bw[8];
        unsigned wp0 = wpb + lro * (WSTR * 2) + lco;
        ldsm4t(bw,     wp0);
        ldsm4t(bw + 4, wp0 + 32);
        unsigned av[4];
#pragma unroll
        for (int m = 0; m < 2; m++) {
            ldsm4(av, abase + (16 * m + lro) * A2B + lco);
            mma16816(acc[m][0], av, bw[0], bw[1]);
            mma16816(acc[m][1], av, bw[2], bw[3]);
            mma16816(acc[m][2], av, bw[4], bw[5]);
            mma16816(acc[m][3], av, bw[6], bw[7]);
        }
        __syncwarp();
    }

    // ---- 9 conv taps (K=32) ----
#pragma unroll
    for (int k = 0; k < K2; k++) {
        uint4* cur = g[k & 1];
        ((uint4*)arow_c)[0] = cur[0];
        ((uint4*)arow_c)[1] = cur[1];
        ((uint4*)arow_c)[2] = cur[2];
        ((uint4*)arow_c)[3] = cur[3];
        __syncwarp();
        if (k < K2 - 1) {
            int ci = (v < n) ? __ldg(g_cidx + (size_t)(k + 1) * n + v) : -1;
            const char* p = (ci >= 0) ? (const char*)(g_h1h + (size_t)ci * COUT)
                                      : (const char*)g_zrow;
            uint4* nxt = g[(k + 1) & 1];
            ldg256(p,      nxt[0], nxt[1]);
            ldg256(p + 32, nxt[2], nxt[3]);
        }
        unsigned wtap = wb0 + k * (COUT * WSTR * 2);
#pragma unroll
        for (int kt = 0; kt < 2; kt++) {
            unsigned bw[8];
            unsigned wk = wtap + (16 * kt + lro) * (WSTR * 2) + lco;
            ldsm4t(bw,     wk);
            ldsm4t(bw + 4, wk + 32);
            unsigned av[4];
#pragma unroll
            for (int m = 0; m < 2; m++) {
                ldsm4(av, abase + (16 * m + lro) * A2B + kt * 32 + lco);
                mma16816(acc[m][0], av, bw[0], bw[1]);
                mma16816(acc[m][1], av, bw[2], bw[3]);
                mma16816(acc[m][2], av, bw[4], bw[5]);
                mma16816(acc[m][3], av, bw[6], bw[7]);
            }
        }
        __syncwarp();
    }

    // epilogue: relu -> fp32 out
#pragma unroll
    for (int m = 0; m < 2; m++) {
        int vg0 = v0w + 16 * m + grp, vg1 = vg0 + 8;
#pragma unroll
        for (int nt = 0; nt < 4; nt++) {
            const float* a = acc[m][nt];
            if (vg0 < n)
                *(float2*)(out + (size_t)vg0 * COUT + 8 * nt + 2 * tig) =
                    make_float2(fmaxf(a[0], 0.f), fmaxf(a[1], 0.f));
            if (vg1 < n)
                *(float2*)(out + (size_t)vg1 * COUT + 8 * nt + 2 * tig) =
                    make_float2(fmaxf(a[2], 0.f), fmaxf(a[3], 0.f));
        }
    }
}

// =====================================================================
// Launch.  Input order: x, W1, b1, W2, b2, Wp, bp, nbr_idx, nbr_mask
// =====================================================================
extern "C" void kernel_launch(void* const* d_in, const int* in_sizes, int n_in,
                              void* d_out, int out_size) {
    const float* x  = (const float*)d_in[0];
    const float* W1 = (const float*)d_in[1];
    const float* b1 = (const float*)d_in[2];
    const float* W2 = (const float*)d_in[3];
    const float* b2 = (const float*)d_in[4];
    const float* Wp = (const float*)d_in[5];
    const float* bp = (const float*)d_in[6];
    const int* nbr_idx = (const int*)d_in[7];
    const unsigned* nbr_mask = (const unsigned*)d_in[8];
    float* out = (float*)d_out;

    int n = in_sizes[0] / CIN;
    if (n > MAXN) n = MAXN;

    fuse_kernel<<<1024, 256>>>(nbr_idx, nbr_mask, K2 * n);
    xh_kernel<<<512, 256>>>(x, n);
    wcvt_kernel<<<(K2 * COUT * COUT + 255) / 256, 256>>>(W1, W2, Wp);

    int blocks = (n + 255) / 256;
    conv1_kernel<<<blocks, 256>>>(b1, n);
    conv2_kernel<<<blocks, 256>>>(b2, bp, out, n);
}

// round 11
// speedup vs baseline: 6.0839x; 1.3255x over previous
#include <cuda_runtime.h>
#include <cuda_fp16.h>
#include <cstdint>

#define CIN 16
#define COUT 32
#define K2 9
#define MAXN 2000000
#define WSTR 40    // weight SMEM row stride in halves (80 B)
#define A2B 80     // conv2 A-tile row stride bytes
#define A1B 48     // conv1 A-tile row stride bytes

// fp16 intermediate h1 (128 MB ~ L2-resident) and fp16 copy of x (64 MB).
__device__ __align__(256) __half g_h1h[(size_t)MAXN * COUT];
__device__ __align__(256) __half g_xh[(size_t)MAXN * CIN];
// fused gather index: cidx = mask ? idx : -1
__device__ int g_cidx[(size_t)K2 * MAXN];
// fp16 weights (compact)
__device__ __half g_w1h[K2 * CIN * COUT];
__device__ __half g_w2h[K2 * COUT * COUT];
__device__ __half g_wph[CIN * COUT];
// zero row (64 B) for masked / out-of-range gathers
__device__ __align__(64) unsigned g_zrow[16] = {};

// ---- PTX wrappers ----
__device__ __forceinline__ void ldg256(const void* p, uint4& a, uint4& b) {
    asm("ld.global.nc.v8.b32 {%0,%1,%2,%3,%4,%5,%6,%7}, [%8];"
        : "=r"(a.x), "=r"(a.y), "=r"(a.z), "=r"(a.w),
          "=r"(b.x), "=r"(b.y), "=r"(b.z), "=r"(b.w)
        : "l"(p));
}
__device__ __forceinline__ void ldsm4(unsigned r[4], unsigned addr) {
    asm volatile("ldmatrix.sync.aligned.m8n8.x4.shared.b16 {%0,%1,%2,%3}, [%4];"
                 : "=r"(r[0]), "=r"(r[1]), "=r"(r[2]), "=r"(r[3]) : "r"(addr));
}
__device__ __forceinline__ void ldsm4t(unsigned r[4], unsigned addr) {
    asm volatile("ldmatrix.sync.aligned.m8n8.x4.trans.shared.b16 {%0,%1,%2,%3}, [%4];"
                 : "=r"(r[0]), "=r"(r[1]), "=r"(r[2]), "=r"(r[3]) : "r"(addr));
}
__device__ __forceinline__ void mma16816(float c[4], const unsigned a[4],
                                         unsigned b0, unsigned b1) {
    asm("mma.sync.aligned.m16n8k16.row.col.f32.f16.f16.f32 "
        "{%0,%1,%2,%3}, {%4,%5,%6,%7}, {%8,%9}, {%0,%1,%2,%3};"
        : "+f"(c[0]), "+f"(c[1]), "+f"(c[2]), "+f"(c[3])
        : "r"(a[0]), "r"(a[1]), "r"(a[2]), "r"(a[3]), "r"(b0), "r"(b1));
}

// =====================================================================
// prologues
// =====================================================================
__global__ __launch_bounds__(256)
void fuse_kernel(const int* __restrict__ idx, const unsigned* __restrict__ mask, int total) {
    int i = blockIdx.x * blockDim.x + threadIdx.x;
    int stride = gridDim.x * blockDim.x;
    int t4 = total >> 2;
    const int4* i4 = (const int4*)idx;
    const uint4* m4 = (const uint4*)mask;
    int4* c4 = (int4*)g_cidx;
    for (int j = i; j < t4; j += stride) {
        int4 v = i4[j]; uint4 m = m4[j];
        v.x = m.x ? v.x : -1;  v.y = m.y ? v.y : -1;
        v.z = m.z ? v.z : -1;  v.w = m.w ? v.w : -1;
        c4[j] = v;
    }
    if (i == 0)
        for (int j = t4 * 4; j < total; j++) g_cidx[j] = mask[j] ? idx[j] : -1;
}

__global__ __launch_bounds__(256)
void xh_kernel(const float* __restrict__ x, int n) {
    int total8 = n * CIN / 8;
    int stride = gridDim.x * blockDim.x;
    const float4* x4 = (const float4*)x;
    uint4* o4 = (uint4*)g_xh;
    for (int j = blockIdx.x * blockDim.x + threadIdx.x; j < total8; j += stride) {
        float4 a = __ldg(x4 + 2 * j), b = __ldg(x4 + 2 * j + 1);
        uint4 o; __half2 h;
        h = __floats2half2_rn(a.x, a.y); o.x = *(unsigned*)&h;
        h = __floats2half2_rn(a.z, a.w); o.y = *(unsigned*)&h;
        h = __floats2half2_rn(b.x, b.y); o.z = *(unsigned*)&h;
        h = __floats2half2_rn(b.z, b.w); o.w = *(unsigned*)&h;
        o4[j] = o;
    }
}

__global__ __launch_bounds__(256)
void wcvt_kernel(const float* __restrict__ W1, const float* __restrict__ W2,
                 const float* __restrict__ Wp) {
    int i = blockIdx.x * 256 + threadIdx.x;
    if (i < K2 * CIN * COUT)  g_w1h[i] = __float2half(W1[i]);
    if (i < K2 * COUT * COUT) g_w2h[i] = __float2half(W2[i]);
    if (i < CIN * COUT)       g_wph[i] = __float2half(Wp[i]);
}

// =====================================================================
// conv1: h1(fp16) = relu( sum_k x_h[cidx] @ W1[k] + b1 )
// warp tile M=64 (2 rows/lane), depth-2 gather prefetch.
// =====================================================================
__global__ __launch_bounds__(256, 2)
void conv1_kernel(const float* __restrict__ b1, int n) {
    __shared__ __half wsm[K2 * CIN * WSTR];                  // 11.5 KB
    __shared__ float bsm[COUT];
    __shared__ __align__(16) __half atile[8 * 64 * (A1B / 2)];  // 24 KB

    const int t = threadIdx.x, lane = t & 31, w = t >> 5;
    for (int i = t; i < K2 * CIN * COUT; i += 256) {
        int row = i >> 5, cc = i & 31;
        wsm[row * WSTR + cc] = g_w1h[i];
    }
    if (t < COUT) bsm[t] = __ldg(b1 + t);
    __syncthreads();

    const int grp = lane >> 2, tig = lane & 3;
    const int sub = lane & 7, ti = lane >> 3;
    const int v0w = blockIdx.x * 512 + w * 64;
    const int vA = v0w + lane, vB = vA + 32;

    char* arowA = (char*)atile + w * 64 * A1B + lane * A1B;
    char* arowB = arowA + 32 * A1B;
    const unsigned abase =
        (unsigned)__cvta_generic_to_shared((char*)atile + w * 64 * A1B);
    const unsigned wb0 = (unsigned)__cvta_generic_to_shared(wsm);
    const int lro = sub + ((ti & 1) << 3);
    const int lco = (ti >> 1) << 4;

    float acc[4][4][4];
#pragma unroll
    for (int m = 0; m < 4; m++)
#pragma unroll
        for (int nt = 0; nt < 4; nt++) {
            float c0 = bsm[8 * nt + 2 * tig], c1 = bsm[8 * nt + 2 * tig + 1];
            acc[m][nt][0] = c0; acc[m][nt][1] = c1;
            acc[m][nt][2] = c0; acc[m][nt][3] = c1;
        }

    uint4 gA[2][2], gB[2][2];
    auto load1 = [&](int k, int buf) {
        int ciA = (vA < n) ? __ldg(g_cidx + (size_t)k * n + vA) : -1;
        int ciB = (vB < n) ? __ldg(g_cidx + (size_t)k * n + vB) : -1;
        const void* pA = (ciA >= 0) ? (const void*)(g_xh + (size_t)ciA * CIN)
                                    : (const void*)g_zrow;
        const void* pB = (ciB >= 0) ? (const void*)(g_xh + (size_t)ciB * CIN)
                                    : (const void*)g_zrow;
        ldg256(pA, gA[buf][0], gA[buf][1]);
        ldg256(pB, gB[buf][0], gB[buf][1]);
    };

    load1(0, 0);
    load1(1, 1);

#pragma unroll
    for (int k = 0; k < K2; k++) {
        int cur = k & 1;
        ((uint4*)arowA)[0] = gA[cur][0];
        ((uint4*)arowA)[1] = gA[cur][1];
        ((uint4*)arowB)[0] = gB[cur][0];
        ((uint4*)arowB)[1] = gB[cur][1];
        __syncwarp();
        if (k + 2 < K2) load1(k + 2, cur);
        unsigned bw[8];
        unsigned wtap = wb0 + k * (CIN * WSTR * 2) + lro * (WSTR * 2) + lco;
        ldsm4t(bw,     wtap);
        ldsm4t(bw + 4, wtap + 32);
#pragma unroll
        for (int m = 0; m < 4; m++) {
            unsigned av[4];
            ldsm4(av, abase + (16 * m + lro) * A1B + lco);
            mma16816(acc[m][0], av, bw[0], bw[1]);
            mma16816(acc[m][1], av, bw[2], bw[3]);
            mma16816(acc[m][2], av, bw[4], bw[5]);
            mma16816(acc[m][3], av, bw[6], bw[7]);
        }
        __syncwarp();
    }

    // epilogue: relu -> fp16 h1
#pragma unroll
    for (int m = 0; m < 4; m++) {
        int vg0 = v0w + 16 * m + grp, vg1 = vg0 + 8;
#pragma unroll
        for (int nt = 0; nt < 4; nt++) {
            const float* a = acc[m][nt];
            if (vg0 < n) {
                __half2 h = __floats2half2_rn(fmaxf(a[0], 0.f), fmaxf(a[1], 0.f));
                *(__half2*)(g_h1h + (size_t)vg0 * COUT + 8 * nt + 2 * tig) = h;
            }
            if (vg1 < n) {
                __half2 h = __floats2half2_rn(fmaxf(a[2], 0.f), fmaxf(a[3], 0.f));
                *(__half2*)(g_h1h + (size_t)vg1 * COUT + 8 * nt + 2 * tig) = h;
            }
        }
    }
}

// =====================================================================
// conv2 + residual: out = relu( sum_k h1[cidx] @ W2[k] + x_h @ Wp + b2 + bp )
// warp tile M=64, K=32 per tap -> 32 HMMA/tap; single-buffer staging.
// =====================================================================
__global__ __launch_bounds__(256, 2)
void conv2_kernel(const float* __restrict__ b2, const float* __restrict__ bp,
                  float* __restrict__ out, int n) {
    extern __shared__ char smem[];
    __half* atile = (__half*)smem;                              // 8*64*80 = 40960 B
    __half* wsm   = (__half*)(smem + 8 * 64 * A2B);             // 23040 B
    __half* wpsm  = wsm + K2 * COUT * WSTR;                     // 1280 B
    float*  bsm   = (float*)(wpsm + CIN * WSTR);                // 128 B

    const int t = threadIdx.x, lane = t & 31, w = t >> 5;
    for (int i = t; i < K2 * COUT * COUT; i += 256) {
        int row = i >> 5, cc = i & 31;
        wsm[row * WSTR + cc] = g_w2h[i];
    }
    for (int i = t; i < CIN * COUT; i += 256) {
        int row = i >> 5, cc = i & 31;
        wpsm[row * WSTR + cc] = g_wph[i];
    }
    if (t < COUT) bsm[t] = __ldg(b2 + t) + __ldg(bp + t);
    __syncthreads();

    const int grp = lane >> 2, tig = lane & 3;
    const int sub = lane & 7, ti = lane >> 3;
    const int v0w = blockIdx.x * 512 + w * 64;
    const int vA = v0w + lane, vB = vA + 32;

    char* arowA = (char*)atile + w * 64 * A2B + lane * A2B;
    char* arowB = arowA + 32 * A2B;
    const unsigned abase =
        (unsigned)__cvta_generic_to_shared((char*)atile + w * 64 * A2B);
    const unsigned wb0 = (unsigned)__cvta_generic_to_shared(wsm);
    const unsigned wpb = (unsigned)__cvta_generic_to_shared(wpsm);
    const int lro = sub + ((ti & 1) << 3);
    const int lco = (ti >> 1) << 4;

    float acc[4][4][4];
#pragma unroll
    for (int m = 0; m < 4; m++)
#pragma unroll
        for (int nt = 0; nt < 4; nt++) {
            float c0 = bsm[8 * nt + 2 * tig], c1 = bsm[8 * nt + 2 * tig + 1];
            acc[m][nt][0] = c0; acc[m][nt][1] = c1;
            acc[m][nt][2] = c0; acc[m][nt][3] = c1;
        }

    // ---- projection tap (K=16) from own fp16 x rows ----
    {
        uint4 p0, p1;
        const void* xp = (vA < n) ? (const void*)(g_xh + (size_t)vA * CIN)
                                  : (const void*)g_zrow;
        ldg256(xp, p0, p1);
        ((uint4*)arowA)[0] = p0;
        ((uint4*)arowA)[1] = p1;
        const void* xq = (vB < n) ? (const void*)(g_xh + (size_t)vB * CIN)
                                  : (const void*)g_zrow;
        ldg256(xq, p0, p1);
        ((uint4*)arowB)[0] = p0;
        ((uint4*)arowB)[1] = p1;
        __syncwarp();
    }

    // single-buffer staging for conv taps (regs freed at STS issue)
    uint4 gA[4], gB[4];
    auto load2 = [&](int k) {
        int ciA = (vA < n) ? __ldg(g_cidx + (size_t)k * n + vA) : -1;
        int ciB = (vB < n) ? __ldg(g_cidx + (size_t)k * n + vB) : -1;
        const char* pA = (ciA >= 0) ? (const char*)(g_h1h + (size_t)ciA * COUT)
                                    : (const char*)g_zrow;
        const char* pB = (ciB >= 0) ? (const char*)(g_h1h + (size_t)ciB * COUT)
                                    : (const char*)g_zrow;
        ldg256(pA,      gA[0], gA[1]);
        ldg256(pA + 32, gA[2], gA[3]);
        ldg256(pB,      gB[0], gB[1]);
        ldg256(pB + 32, gB[2], gB[3]);
    };
    load2(0);     // overlap with proj MMA

    // proj MMA (K=16)
    {
        unsigned bw[8];
        unsigned wp0 = wpb + lro * (WSTR * 2) + lco;
        ldsm4t(bw,     wp0);
        ldsm4t(bw + 4, wp0 + 32);
#pragma unroll
        for (int m = 0; m < 4; m++) {
            unsigned av[4];
            ldsm4(av, abase + (16 * m + lro) * A2B + lco);
            mma16816(acc[m][0], av, bw[0], bw[1]);
            mma16816(acc[m][1], av, bw[2], bw[3]);
            mma16816(acc[m][2], av, bw[4], bw[5]);
            mma16816(acc[m][3], av, bw[6], bw[7]);
        }
        __syncwarp();
    }

    // ---- 9 conv taps (K=32) ----
#pragma unroll
    for (int k = 0; k < K2; k++) {
        ((uint4*)arowA)[0] = gA[0];
        ((uint4*)arowA)[1] = gA[1];
        ((uint4*)arowA)[2] = gA[2];
        ((uint4*)arowA)[3] = gA[3];
        ((uint4*)arowB)[0] = gB[0];
        ((uint4*)arowB)[1] = gB[1];
        ((uint4*)arowB)[2] = gB[2];
        ((uint4*)arowB)[3] = gB[3];
        __syncwarp();
        if (k + 1 < K2) load2(k + 1);
        unsigned wtap = wb0 + k * (COUT * WSTR * 2);
#pragma unroll
        for (int kt = 0; kt < 2; kt++) {
            unsigned bw[8];
            unsigned wk = wtap + (16 * kt + lro) * (WSTR * 2) + lco;
            ldsm4t(bw,     wk);
            ldsm4t(bw + 4, wk + 32);
#pragma unroll
            for (int m = 0; m < 4; m++) {
                unsigned av[4];
                ldsm4(av, abase + (16 * m + lro) * A2B + kt * 32 + lco);
                mma16816(acc[m][0], av, bw[0], bw[1]);
                mma16816(acc[m][1], av, bw[2], bw[3]);
                mma16816(acc[m][2], av, bw[4], bw[5]);
                mma16816(acc[m][3], av, bw[6], bw[7]);
            }
        }
        __syncwarp();
    }

    // epilogue: relu -> fp32 out
#pragma unroll
    for (int m = 0; m < 4; m++) {
        int vg0 = v0w + 16 * m + grp, vg1 = vg0 + 8;
#pragma unroll
        for (int nt = 0; nt < 4; nt++) {
            const float* a = acc[m][nt];
            if (vg0 < n)
                *(float2*)(out + (size_t)vg0 * COUT + 8 * nt + 2 * tig) =
                    make_float2(fmaxf(a[0], 0.f), fmaxf(a[1], 0.f));
            if (vg1 < n)
                *(float2*)(out + (size_t)vg1 * COUT + 8 * nt + 2 * tig) =
                    make_float2(fmaxf(a[2], 0.f), fmaxf(a[3], 0.f));
        }
    }
}

// =====================================================================
// Launch.  Input order: x, W1, b1, W2, b2, Wp, bp, nbr_idx, nbr_mask
// =====================================================================
extern "C" void kernel_launch(void* const* d_in, const int* in_sizes, int n_in,
                              void* d_out, int out_size) {
    const float* x  = (const float*)d_in[0];
    const float* W1 = (const float*)d_in[1];
    const float* b1 = (const float*)d_in[2];
    const float* W2 = (const float*)d_in[3];
    const float* b2 = (const float*)d_in[4];
    const float* Wp = (const float*)d_in[5];
    const float* bp = (const float*)d_in[6];
    const int* nbr_idx = (const int*)d_in[7];
    const unsigned* nbr_mask = (const unsigned*)d_in[8];
    float* out = (float*)d_out;

    int n = in_sizes[0] / CIN;
    if (n > MAXN) n = MAXN;

    const int smem2 = 8 * 64 * A2B + K2 * COUT * WSTR * 2 + CIN * WSTR * 2 + COUT * 4;
    cudaFuncSetAttribute(conv2_kernel, cudaFuncAttributeMaxDynamicSharedMemorySize, smem2);

    fuse_kernel<<<1024, 256>>>(nbr_idx, nbr_mask, K2 * n);
    xh_kernel<<<512, 256>>>(x, n);
    wcvt_kernel<<<(K2 * COUT * COUT + 255) / 256, 256>>>(W1, W2, Wp);

    int blocks = (n + 511) / 512;
    conv1_kernel<<<blocks, 256>>>(b1, n);
    conv2_kernel<<<blocks, 256, smem2>>>(b2, bp, out, n);
}